// round 2
// baseline (speedup 1.0000x reference)
#include <cuda_runtime.h>
#include <math.h>
#include <stdint.h>

#define B_  32
#define TZ_ 16
#define TU_ 128
#define E_  512
#define H_  1024
#define V_  32000
#define XD_ (E_ + 2*H_)     // 2560
#define LN_EPS_ 1e-3f
#define FREQ_ 4

// ---------------- scratch (device global, no allocs) ----------------
// offsets in floats
#define OFF_EU     0                         // 4096*1024
#define OFF_EZ     (OFF_EU + TU_*B_*H_)      // 512*1024
#define OFF_HPZ    (OFF_EZ + TZ_*B_*H_)
#define OFF_HPU    (OFF_HPZ + B_*H_)
#define OFF_X      (OFF_HPU + B_*H_)         // B x 2560
#define OFF_GI     (OFF_X + B_*XD_)          // B x 3H
#define OFF_GH     (OFF_GI + B_*3*H_)
#define OFF_GRU    (OFF_GH + B_*3*H_)        // B x H
#define OFF_GEN    (OFF_GRU + B_*H_)         // B x V
#define OFF_GPART  (OFF_GEN + B_*V_)         // B x H
#define OFF_ZCLIN  (OFF_GPART + B_*H_)       // TZ*B x H
#define OFF_SCZ    (OFF_ZCLIN + TZ_*B_*H_)   // B x TZ
#define OFF_SCU    (OFF_SCZ + B_*TZ_)        // B x TU
#define OFF_ZC     (OFF_SCU + B_*TU_)        // B x TZ
#define OFF_MX     (OFF_ZC + B_*TZ_)
#define OFF_IS     (OFF_MX + B_)
#define OFF_CP     (OFF_IS + B_)             // B x TZ
#define SCRATCH_TOTAL (OFF_CP + B_*TZ_)

__device__ float g_scratch[SCRATCH_TOTAL];

// ---------------- reductions ----------------
__device__ __forceinline__ float warpSum(float v) {
    #pragma unroll
    for (int o = 16; o; o >>= 1) v += __shfl_down_sync(0xffffffffu, v, o);
    return v;
}
__device__ __forceinline__ float warpMax(float v) {
    #pragma unroll
    for (int o = 16; o; o >>= 1) v = fmaxf(v, __shfl_down_sync(0xffffffffu, v, o));
    return v;
}
__device__ float blockSum(float v) {
    __shared__ float sh[32];
    int lane = threadIdx.x & 31, wid = threadIdx.x >> 5;
    v = warpSum(v);
    if (lane == 0) sh[wid] = v;
    __syncthreads();
    v = (threadIdx.x < (blockDim.x >> 5)) ? sh[lane] : 0.f;
    if (wid == 0) v = warpSum(v);
    __syncthreads();
    return v;  // valid in thread 0
}
__device__ float blockMax(float v) {
    __shared__ float sh[32];
    int lane = threadIdx.x & 31, wid = threadIdx.x >> 5;
    v = warpMax(v);
    if (lane == 0) sh[wid] = v;
    __syncthreads();
    v = (threadIdx.x < (blockDim.x >> 5)) ? sh[lane] : -1e30f;
    if (wid == 0) v = warpMax(v);
    __syncthreads();
    return v;  // valid in thread 0
}

// ---------------- tiled SGEMM: C[M,N] = A[M,K] @ op(B)  (row-major) ----------------
// transB==0: B is K x N ;  transB==1: B is N x K (C = A @ B^T)
#define TILE 64
#define BK 16
__global__ __launch_bounds__(256) void sgemm_tiled(
    const float* __restrict__ A, const float* __restrict__ Bm,
    const float* __restrict__ bias, float* __restrict__ C,
    int M, int N, int K, int transB)
{
    __shared__ float As[BK][TILE];
    __shared__ float Bs[BK][TILE + 1];
    int bm = blockIdx.y * TILE;
    int bn = blockIdx.x * TILE;
    int tid = threadIdx.x;
    int tx = tid & 15;   // n
    int ty = tid >> 4;   // m
    float acc[4][4] = {};
    for (int k0 = 0; k0 < K; k0 += BK) {
        #pragma unroll
        for (int i = tid; i < TILE * BK; i += 256) {
            int m = i / BK, k = i % BK;
            int gm = bm + m, gk = k0 + k;
            As[k][m] = (gm < M && gk < K) ? A[(size_t)gm * K + gk] : 0.f;
        }
        #pragma unroll
        for (int i = tid; i < TILE * BK; i += 256) {
            int n = i % TILE, k = i / TILE;
            int gn = bn + n, gk = k0 + k;
            float v = 0.f;
            if (gn < N && gk < K)
                v = transB ? Bm[(size_t)gn * K + gk] : Bm[(size_t)gk * N + gn];
            Bs[k][n] = v;
        }
        __syncthreads();
        #pragma unroll
        for (int k = 0; k < BK; k++) {
            float a[4], b[4];
            #pragma unroll
            for (int i = 0; i < 4; i++) a[i] = As[k][ty * 4 + i];
            #pragma unroll
            for (int j = 0; j < 4; j++) b[j] = Bs[k][tx * 4 + j];
            #pragma unroll
            for (int i = 0; i < 4; i++)
                #pragma unroll
                for (int j = 0; j < 4; j++) acc[i][j] += a[i] * b[j];
        }
        __syncthreads();
    }
    #pragma unroll
    for (int i = 0; i < 4; i++) {
        int gm = bm + ty * 4 + i;
        if (gm >= M) continue;
        #pragma unroll
        for (int j = 0; j < 4; j++) {
            int gn = bn + tx * 4 + j;
            if (gn >= N) continue;
            float v = acc[i][j];
            if (bias) v += bias[gn];
            C[(size_t)gm * N + gn] = v;
        }
    }
}

// ---------------- skinny SGEMM (M == 32): each thread owns one output column ----------------
__global__ __launch_bounds__(256) void sgemm_skinny32(
    const float* __restrict__ A, const float* __restrict__ Bm,
    const float* __restrict__ bias, float* __restrict__ C,
    int N, int K, int transB)
{
    __shared__ float As[32][33];  // [k][m]
    int n = blockIdx.x * blockDim.x + threadIdx.x;
    float acc[32];
    #pragma unroll
    for (int m = 0; m < 32; m++) acc[m] = 0.f;
    for (int k0 = 0; k0 < K; k0 += 32) {
        for (int i = threadIdx.x; i < 32 * 32; i += blockDim.x) {
            int m = i >> 5, k = i & 31;
            As[k][m] = A[(size_t)m * K + k0 + k];
        }
        __syncthreads();
        if (n < N) {
            #pragma unroll 4
            for (int k = 0; k < 32; k++) {
                float b = transB ? Bm[(size_t)n * K + k0 + k]
                                 : Bm[(size_t)(k0 + k) * N + n];
                #pragma unroll
                for (int m = 0; m < 32; m++) acc[m] = fmaf(As[k][m], b, acc[m]);
            }
        }
        __syncthreads();
    }
    if (n < N) {
        float bv = bias ? bias[n] : 0.f;
        #pragma unroll
        for (int m = 0; m < 32; m++) C[(size_t)m * N + n] = acc[m] + bv;
    }
}

// ---------------- embedding gather into x[:, 2H:2H+E] ----------------
__global__ void k_emb(const float* __restrict__ emb, const int* __restrict__ mt,
                      float* __restrict__ x)
{
    int b = blockIdx.x;
    int tok = mt[b];
    for (int e = threadIdx.x; e < E_; e += blockDim.x)
        x[b * XD_ + 2 * H_ + e] = emb[(size_t)tok * E_ + e];
}

// ---------------- attention scores: sc[b,t] = v . tanh(hp[b]+Epart[t,b]+ba) ----------------
__global__ void k_score(const float* __restrict__ Ep, const float* __restrict__ hp,
                        const float* __restrict__ ba, const float* __restrict__ v,
                        float* __restrict__ sc, int T)
{
    int tb = blockIdx.x;          // t*B + b
    int t = tb / B_, b = tb % B_;
    float s = 0.f;
    for (int h = threadIdx.x; h < H_; h += blockDim.x)
        s += v[h] * tanhf(Ep[(size_t)tb * H_ + h] + hp[b * H_ + h] + ba[h]);
    s = blockSum(s);
    if (threadIdx.x == 0) sc[b * T + t] = s;
}

// ---------------- softmax over t + context into x[:, xoff:xoff+H] ----------------
__global__ void k_softmax_ctx(const float* __restrict__ sc, const float* __restrict__ enc,
                              float* __restrict__ x, int T, int xoff)
{
    int b = blockIdx.x;
    __shared__ float w[TU_];
    if (threadIdx.x == 0) {
        float mx = -1e30f;
        for (int t = 0; t < T; t++) mx = fmaxf(mx, sc[b * T + t]);
        float S = 0.f;
        for (int t = 0; t < T; t++) { float e = expf(sc[b * T + t] - mx); w[t] = e; S += e; }
        float inv = 1.f / S;
        for (int t = 0; t < T; t++) w[t] *= inv;
    }
    __syncthreads();
    for (int h = threadIdx.x; h < H_; h += blockDim.x) {
        float acc = 0.f;
        for (int t = 0; t < T; t++)
            acc += w[t] * enc[((size_t)t * B_ + b) * H_ + h];
        x[b * XD_ + xoff + h] = acc;
    }
}

// ---------------- GRU cell + layernorm (ddof=1, /(sigma+eps)) ----------------
__global__ void k_gru_ln(const float* __restrict__ gi, const float* __restrict__ gh,
                         const float* __restrict__ hprev,
                         const float* __restrict__ la, const float* __restrict__ lb,
                         float* __restrict__ gru_out, float* __restrict__ hnew_out)
{
    int b = blockIdx.x;
    __shared__ float hn[H_];
    __shared__ float mu_s, sig_s;
    for (int h = threadIdx.x; h < H_; h += blockDim.x) {
        float ir = gi[b * 3 * H_ + h];
        float iz = gi[b * 3 * H_ + H_ + h];
        float in = gi[b * 3 * H_ + 2 * H_ + h];
        float hr = gh[b * 3 * H_ + h];
        float hz = gh[b * 3 * H_ + H_ + h];
        float hnn = gh[b * 3 * H_ + 2 * H_ + h];
        float r  = 1.f / (1.f + expf(-(ir + hr)));
        float zg = 1.f / (1.f + expf(-(iz + hz)));
        float n  = tanhf(in + r * hnn);
        float hp = hprev[b * H_ + h];
        hn[h] = (1.f - zg) * n + zg * hp;
    }
    __syncthreads();
    float s = 0.f;
    for (int h = threadIdx.x; h < H_; h += blockDim.x) s += hn[h];
    s = blockSum(s);
    if (threadIdx.x == 0) mu_s = s / H_;
    __syncthreads();
    float mu = mu_s;
    float vs = 0.f;
    for (int h = threadIdx.x; h < H_; h += blockDim.x) { float d = hn[h] - mu; vs += d * d; }
    vs = blockSum(vs);
    if (threadIdx.x == 0) sig_s = sqrtf(vs / (float)(H_ - 1));
    __syncthreads();
    float inv = 1.f / (sig_s + LN_EPS_);
    for (int h = threadIdx.x; h < H_; h += blockDim.x) {
        gru_out[b * H_ + h] = (hn[h] - mu) * inv * la[h] + lb[h];
        hnew_out[b * H_ + h] = hn[h];
    }
}

// ---------------- copy-attention scores: zc[b,t] = Wv1 . tanh(zclin[t,b]+gpart[b]+bc) + bv1 ----
__global__ void k_zc(const float* __restrict__ zclin, const float* __restrict__ gpart,
                     const float* __restrict__ bc, const float* __restrict__ Wv1,
                     const float* __restrict__ bv1, float* __restrict__ zc)
{
    int tb = blockIdx.x;
    int t = tb / B_, b = tb % B_;
    float s = 0.f;
    for (int h = threadIdx.x; h < H_; h += blockDim.x)
        s += Wv1[h] * tanhf(zclin[(size_t)tb * H_ + h] + gpart[b * H_ + h] + bc[h]);
    s = blockSum(s);
    if (threadIdx.x == 0) zc[b * TZ_ + t] = s + bv1[0];
}

// ---------------- joint softmax stats over [gen (V), zc (TZ)] ----------------
__global__ void k_stats(const float* __restrict__ gen, const float* __restrict__ zc,
                        float* __restrict__ mx, float* __restrict__ invs,
                        float* __restrict__ cp)
{
    int b = blockIdx.x;
    __shared__ float mbc, sbc;
    float m = -1e30f;
    for (int v = threadIdx.x; v < V_; v += blockDim.x)
        m = fmaxf(m, gen[(size_t)b * V_ + v]);
    if (threadIdx.x < TZ_) m = fmaxf(m, zc[b * TZ_ + threadIdx.x]);
    m = blockMax(m);
    if (threadIdx.x == 0) mbc = m;
    __syncthreads();
    m = mbc;
    float s = 0.f;
    for (int v = threadIdx.x; v < V_; v += blockDim.x)
        s += expf(gen[(size_t)b * V_ + v] - m);
    if (threadIdx.x < TZ_) s += expf(zc[b * TZ_ + threadIdx.x] - m);
    s = blockSum(s);
    if (threadIdx.x == 0) sbc = s;
    __syncthreads();
    float inv = 1.f / sbc;
    if (threadIdx.x == 0) { mx[b] = m; invs[b] = inv; }
    if (threadIdx.x < TZ_)
        cp[b * TZ_ + threadIdx.x] = expf(zc[b * TZ_ + threadIdx.x] - m) * inv;
}

// ---------------- final: proba = gen_p + mask * (copy_p @ pz_proba) ----------------
__global__ void k_write(const float* __restrict__ gen, const float* __restrict__ pz,
                        const float* __restrict__ mx, const float* __restrict__ invs,
                        const float* __restrict__ cp, float* __restrict__ out)
{
    int idx = blockIdx.x * blockDim.x + threadIdx.x;
    if (idx >= B_ * V_) return;
    int b = idx / V_, v = idx % V_;
    float val = expf(gen[idx] - mx[b]) * invs[b];
    if (v >= FREQ_) {
        float cv = 0.f;
        #pragma unroll
        for (int t = 0; t < TZ_; t++)
            cv += cp[b * TZ_ + t] * pz[((size_t)t * B_ + b) * V_ + v];
        val += cv;
    }
    out[idx] = val;
}

// ---------------- launch ----------------
extern "C" void kernel_launch(void* const* d_in, const int* in_sizes, int n_in,
                              void* d_out, int out_size)
{
    const float* z_enc  = (const float*)d_in[0];
    const float* pz     = (const float*)d_in[1];
    const float* u_enc  = (const float*)d_in[2];
    const int*   mt     = (const int*)  d_in[3];
    const float* hid    = (const float*)d_in[4];
    const float* emb    = (const float*)d_in[5];
    const float* Wa_z   = (const float*)d_in[6];
    const float* ba_z   = (const float*)d_in[7];
    const float* v_z    = (const float*)d_in[8];
    const float* Wa_u   = (const float*)d_in[9];
    const float* ba_u   = (const float*)d_in[10];
    const float* v_u    = (const float*)d_in[11];
    const float* W_ih   = (const float*)d_in[12];
    const float* W_hh   = (const float*)d_in[13];
    const float* b_ih   = (const float*)d_in[14];
    const float* b_hh   = (const float*)d_in[15];
    const float* ln_a   = (const float*)d_in[16];
    const float* ln_b   = (const float*)d_in[17];
    const float* W_proj = (const float*)d_in[18];
    const float* b_proj = (const float*)d_in[19];
    const float* W_c    = (const float*)d_in[20];
    const float* b_c    = (const float*)d_in[21];
    const float* W_v1   = (const float*)d_in[22];
    const float* b_v1   = (const float*)d_in[23];
    float* out = (float*)d_out;

    float* S;
    cudaGetSymbolAddress((void**)&S, g_scratch);
    float* Eu    = S + OFF_EU;
    float* Ez    = S + OFF_EZ;
    float* hpz   = S + OFF_HPZ;
    float* hpu   = S + OFF_HPU;
    float* x     = S + OFF_X;
    float* gi    = S + OFF_GI;
    float* gh    = S + OFF_GH;
    float* gru   = S + OFF_GRU;
    float* gen   = S + OFF_GEN;
    float* gpart = S + OFF_GPART;
    float* zclin = S + OFF_ZCLIN;
    float* scz   = S + OFF_SCZ;
    float* scu   = S + OFF_SCU;
    float* zc    = S + OFF_ZC;
    float* mx    = S + OFF_MX;
    float* invs  = S + OFF_IS;
    float* cp    = S + OFF_CP;

    // 1) embedding gather into x[:, 2H:]
    k_emb<<<B_, 128>>>(emb, mt, x);

    // 2) hidden-part projections (M=32): hp = hidden @ Wa[0:H]
    sgemm_skinny32<<<(H_ + 255) / 256, 256>>>(hid, Wa_z, nullptr, hpz, H_, H_, 0);
    sgemm_skinny32<<<(H_ + 255) / 256, 256>>>(hid, Wa_u, nullptr, hpu, H_, H_, 0);

    // 3) encoder-part energies: E = enc_flat @ Wa[H:2H]
    {
        dim3 g((H_ + TILE - 1) / TILE, (TZ_ * B_ + TILE - 1) / TILE);
        sgemm_tiled<<<g, 256>>>(z_enc, Wa_z + (size_t)H_ * H_, nullptr, Ez, TZ_ * B_, H_, H_, 0);
    }
    {
        dim3 g((H_ + TILE - 1) / TILE, (TU_ * B_ + TILE - 1) / TILE);
        sgemm_tiled<<<g, 256>>>(u_enc, Wa_u + (size_t)H_ * H_, nullptr, Eu, TU_ * B_, H_, H_, 0);
    }

    // 4) attention scores + softmax + context
    k_score<<<TZ_ * B_, 256>>>(Ez, hpz, ba_z, v_z, scz, TZ_);
    k_score<<<TU_ * B_, 256>>>(Eu, hpu, ba_u, v_u, scu, TU_);
    k_softmax_ctx<<<B_, 256>>>(scz, z_enc, x, TZ_, 0);
    k_softmax_ctx<<<B_, 256>>>(scu, u_enc, x, TU_, H_);

    // 5) GRU gates: gi = x @ W_ih^T + b_ih ; gh = h @ W_hh^T + b_hh
    sgemm_skinny32<<<(3 * H_ + 255) / 256, 256>>>(x, W_ih, b_ih, gi, 3 * H_, XD_, 1);
    sgemm_skinny32<<<(3 * H_ + 255) / 256, 256>>>(hid, W_hh, b_hh, gh, 3 * H_, H_, 1);

    // 6) GRU + layernorm; h_new goes straight to output tail
    k_gru_ln<<<B_, 256>>>(gi, gh, hid, ln_a, ln_b, gru, out + (size_t)B_ * V_);

    // 7) vocab projection + copy-score path
    sgemm_skinny32<<<(V_ + 255) / 256, 256>>>(gru, W_proj, b_proj, gen, V_, H_, 0);
    sgemm_skinny32<<<(H_ + 255) / 256, 256>>>(gru, W_c + (size_t)H_ * H_, nullptr, gpart, H_, H_, 0);
    {
        dim3 g((H_ + TILE - 1) / TILE, (TZ_ * B_ + TILE - 1) / TILE);
        sgemm_tiled<<<g, 256>>>(z_enc, W_c, nullptr, zclin, TZ_ * B_, H_, H_, 0);
    }
    k_zc<<<TZ_ * B_, 256>>>(zclin, gpart, b_c, W_v1, b_v1, zc);

    // 8) joint softmax + copy mixture
    k_stats<<<B_, 256>>>(gen, zc, mx, invs, cp);
    k_write<<<(B_ * V_ + 255) / 256, 256>>>(gen, pz, mx, invs, cp, out);
}

// round 3
// speedup vs baseline: 3.4292x; 3.4292x over previous
#include <cuda_runtime.h>
#include <math.h>
#include <stdint.h>

#define B_  32
#define TZ_ 16
#define TU_ 128
#define E_  512
#define H_  1024
#define V_  32000
#define XD_ (E_ + 2*H_)     // 2560
#define LN_EPS_ 1e-3f
#define FREQ_ 4

// ---------------- scratch (device global, no allocs) ----------------
#define OFF_EU     0                         // 4096*1024
#define OFF_EZ     (OFF_EU + TU_*B_*H_)      // 512*1024
#define OFF_HPZ    (OFF_EZ + TZ_*B_*H_)
#define OFF_HPU    (OFF_HPZ + B_*H_)
#define OFF_X      (OFF_HPU + B_*H_)         // B x 2560
#define OFF_GI     (OFF_X + B_*XD_)          // B x 3H
#define OFF_GH     (OFF_GI + B_*3*H_)
#define OFF_GRU    (OFF_GH + B_*3*H_)        // B x H
#define OFF_GEN    (OFF_GRU + B_*H_)         // B x V
#define OFF_GPART  (OFF_GEN + B_*V_)         // B x H
#define OFF_ZCLIN  (OFF_GPART + B_*H_)       // TZ*B x H
#define OFF_SCZ    (OFF_ZCLIN + TZ_*B_*H_)   // B x TZ
#define OFF_SCU    (OFF_SCZ + B_*TZ_)        // B x TU
#define OFF_ZC     (OFF_SCU + B_*TU_)        // B x TZ
#define OFF_MX     (OFF_ZC + B_*TZ_)
#define OFF_IS     (OFF_MX + B_)
#define OFF_CP     (OFF_IS + B_)             // B x TZ
#define SCRATCH_TOTAL (OFF_CP + B_*TZ_)

__device__ float g_scratch[SCRATCH_TOTAL];

// ---------------- helpers ----------------
__device__ __forceinline__ float f2tf32(float f) {
    uint32_t u;
    asm("cvt.rna.tf32.f32 %0, %1;" : "=r"(u) : "f"(f));
    return __uint_as_float(u);
}

__device__ __forceinline__ float warpSum(float v) {
    #pragma unroll
    for (int o = 16; o; o >>= 1) v += __shfl_down_sync(0xffffffffu, v, o);
    return v;
}
__device__ __forceinline__ float warpMax(float v) {
    #pragma unroll
    for (int o = 16; o; o >>= 1) v = fmaxf(v, __shfl_down_sync(0xffffffffu, v, o));
    return v;
}
__device__ float blockSum(float v) {
    __shared__ float sh[32];
    int lane = threadIdx.x & 31, wid = threadIdx.x >> 5;
    v = warpSum(v);
    if (lane == 0) sh[wid] = v;
    __syncthreads();
    v = (threadIdx.x < (blockDim.x >> 5)) ? sh[lane] : 0.f;
    if (wid == 0) v = warpSum(v);
    __syncthreads();
    return v;
}
__device__ float blockMax(float v) {
    __shared__ float sh[32];
    int lane = threadIdx.x & 31, wid = threadIdx.x >> 5;
    v = warpMax(v);
    if (lane == 0) sh[wid] = v;
    __syncthreads();
    v = (threadIdx.x < (blockDim.x >> 5)) ? sh[lane] : -1e30f;
    if (wid == 0) v = warpMax(v);
    __syncthreads();
    return v;
}

// ---------------- tf32 tensor-core GEMM ----------------
// C[M,N] = A[M,K] @ op(B) (+bias per column)
// transB==0: B is K x N row-major;  transB==1: B is N x K row-major (C = A @ B^T)
// Requires: M % BM == 0, N % BN == 0, K % BK == 0 (all callers satisfy this).
template<int BM, int BN, int BK, int WARPS_M, int WARPS_N>
__global__ __launch_bounds__(WARPS_M*WARPS_N*32)
void gemm_tf32(const float* __restrict__ A, const float* __restrict__ Bm,
               const float* __restrict__ bias, float* __restrict__ C,
               int M, int N, int K, int transB)
{
    constexpr int NTHREADS = 32 * WARPS_M * WARPS_N;
    constexpr int PAD = 4;
    constexpr int WM = BM / WARPS_M;
    constexpr int WN = BN / WARPS_N;
    constexpr int MT = WM / 16;   // 16-row mma tiles per warp
    constexpr int NTL = WN / 8;   // 8-col mma tiles per warp

    __shared__ float As[BK][BM + PAD];
    __shared__ float Bs[BK][BN + PAD];

    const int tid = threadIdx.x;
    const int wid = tid >> 5, lane = tid & 31;
    const int wm = wid / WARPS_N, wn = wid % WARPS_N;
    const int g = lane >> 2, tg = lane & 3;
    const int bm = blockIdx.y * BM, bn = blockIdx.x * BN;

    float acc[MT][NTL][4];
    #pragma unroll
    for (int i = 0; i < MT; i++)
        #pragma unroll
        for (int j = 0; j < NTL; j++)
            #pragma unroll
            for (int q = 0; q < 4; q++) acc[i][j][q] = 0.f;

    for (int k0 = 0; k0 < K; k0 += BK) {
        // --- load A tile (row-major), convert to tf32, store k-major ---
        #pragma unroll
        for (int i = tid; i < BM * BK / 4; i += NTHREADS) {
            int r = i / (BK / 4), cq = i % (BK / 4);
            float4 v = *(const float4*)&A[(size_t)(bm + r) * K + k0 + cq * 4];
            As[cq * 4 + 0][r] = f2tf32(v.x);
            As[cq * 4 + 1][r] = f2tf32(v.y);
            As[cq * 4 + 2][r] = f2tf32(v.z);
            As[cq * 4 + 3][r] = f2tf32(v.w);
        }
        // --- load B tile ---
        if (!transB) {
            #pragma unroll
            for (int i = tid; i < BK * BN / 4; i += NTHREADS) {
                int r = i / (BN / 4), cq = i % (BN / 4);
                float4 v = *(const float4*)&Bm[(size_t)(k0 + r) * N + bn + cq * 4];
                float4 w;
                w.x = f2tf32(v.x); w.y = f2tf32(v.y);
                w.z = f2tf32(v.z); w.w = f2tf32(v.w);
                *(float4*)&Bs[r][cq * 4] = w;
            }
        } else {
            #pragma unroll
            for (int i = tid; i < BK * BN / 4; i += NTHREADS) {
                int n = i / (BK / 4), kq = i % (BK / 4);
                float4 v = *(const float4*)&Bm[(size_t)(bn + n) * K + k0 + kq * 4];
                Bs[kq * 4 + 0][n] = f2tf32(v.x);
                Bs[kq * 4 + 1][n] = f2tf32(v.y);
                Bs[kq * 4 + 2][n] = f2tf32(v.z);
                Bs[kq * 4 + 3][n] = f2tf32(v.w);
            }
        }
        __syncthreads();

        #pragma unroll
        for (int kk = 0; kk < BK; kk += 8) {
            uint32_t af[MT][4], bf[NTL][2];
            #pragma unroll
            for (int mt = 0; mt < MT; mt++) {
                int r0 = wm * WM + mt * 16 + g;
                af[mt][0] = __float_as_uint(As[kk + tg    ][r0    ]);
                af[mt][1] = __float_as_uint(As[kk + tg    ][r0 + 8]);
                af[mt][2] = __float_as_uint(As[kk + tg + 4][r0    ]);
                af[mt][3] = __float_as_uint(As[kk + tg + 4][r0 + 8]);
            }
            #pragma unroll
            for (int nt = 0; nt < NTL; nt++) {
                int c = wn * WN + nt * 8 + g;
                bf[nt][0] = __float_as_uint(Bs[kk + tg    ][c]);
                bf[nt][1] = __float_as_uint(Bs[kk + tg + 4][c]);
            }
            #pragma unroll
            for (int mt = 0; mt < MT; mt++)
                #pragma unroll
                for (int nt = 0; nt < NTL; nt++) {
                    asm volatile(
                        "mma.sync.aligned.m16n8k8.row.col.f32.tf32.tf32.f32 "
                        "{%0,%1,%2,%3}, {%4,%5,%6,%7}, {%8,%9}, {%0,%1,%2,%3};\n"
                        : "+f"(acc[mt][nt][0]), "+f"(acc[mt][nt][1]),
                          "+f"(acc[mt][nt][2]), "+f"(acc[mt][nt][3])
                        : "r"(af[mt][0]), "r"(af[mt][1]), "r"(af[mt][2]), "r"(af[mt][3]),
                          "r"(bf[nt][0]), "r"(bf[nt][1]));
                }
        }
        __syncthreads();
    }

    // --- epilogue ---
    #pragma unroll
    for (int mt = 0; mt < MT; mt++) {
        int row0 = bm + wm * WM + mt * 16 + g;
        #pragma unroll
        for (int nt = 0; nt < NTL; nt++) {
            int col = bn + wn * WN + nt * 8 + 2 * tg;
            float bv0 = bias ? bias[col]     : 0.f;
            float bv1 = bias ? bias[col + 1] : 0.f;
            C[(size_t)row0 * N + col]           = acc[mt][nt][0] + bv0;
            C[(size_t)row0 * N + col + 1]       = acc[mt][nt][1] + bv1;
            C[(size_t)(row0 + 8) * N + col]     = acc[mt][nt][2] + bv0;
            C[(size_t)(row0 + 8) * N + col + 1] = acc[mt][nt][3] + bv1;
        }
    }
}

// ---------------- embedding gather into x[:, 2H:2H+E] ----------------
__global__ void k_emb(const float* __restrict__ emb, const int* __restrict__ mt,
                      float* __restrict__ x)
{
    int b = blockIdx.x;
    int tok = mt[b];
    for (int e = threadIdx.x; e < E_; e += blockDim.x)
        x[b * XD_ + 2 * H_ + e] = emb[(size_t)tok * E_ + e];
}

// ---------------- attention scores: sc[b,t] = v . tanh(hp[b]+Epart[t,b]+ba) ----------------
__global__ void k_score(const float* __restrict__ Ep, const float* __restrict__ hp,
                        const float* __restrict__ ba, const float* __restrict__ v,
                        float* __restrict__ sc, int T)
{
    int tb = blockIdx.x;          // t*B + b
    int t = tb / B_, b = tb % B_;
    float s = 0.f;
    for (int h = threadIdx.x; h < H_; h += blockDim.x)
        s += v[h] * tanhf(Ep[(size_t)tb * H_ + h] + hp[b * H_ + h] + ba[h]);
    s = blockSum(s);
    if (threadIdx.x == 0) sc[b * T + t] = s;
}

// ---------------- softmax over t + context into x[:, xoff:xoff+H] ----------------
__global__ void k_softmax_ctx(const float* __restrict__ sc, const float* __restrict__ enc,
                              float* __restrict__ x, int T, int xoff)
{
    int b = blockIdx.x;
    __shared__ float w[TU_];
    if (threadIdx.x == 0) {
        float mx = -1e30f;
        for (int t = 0; t < T; t++) mx = fmaxf(mx, sc[b * T + t]);
        float S = 0.f;
        for (int t = 0; t < T; t++) { float e = expf(sc[b * T + t] - mx); w[t] = e; S += e; }
        float inv = 1.f / S;
        for (int t = 0; t < T; t++) w[t] *= inv;
    }
    __syncthreads();
    for (int h = threadIdx.x; h < H_; h += blockDim.x) {
        float acc = 0.f;
        for (int t = 0; t < T; t++)
            acc += w[t] * enc[((size_t)t * B_ + b) * H_ + h];
        x[b * XD_ + xoff + h] = acc;
    }
}

// ---------------- GRU cell + layernorm (ddof=1, /(sigma+eps)) ----------------
__global__ void k_gru_ln(const float* __restrict__ gi, const float* __restrict__ gh,
                         const float* __restrict__ hprev,
                         const float* __restrict__ la, const float* __restrict__ lb,
                         float* __restrict__ gru_out, float* __restrict__ hnew_out)
{
    int b = blockIdx.x;
    __shared__ float hn[H_];
    __shared__ float mu_s, sig_s;
    for (int h = threadIdx.x; h < H_; h += blockDim.x) {
        float ir = gi[b * 3 * H_ + h];
        float iz = gi[b * 3 * H_ + H_ + h];
        float in = gi[b * 3 * H_ + 2 * H_ + h];
        float hr = gh[b * 3 * H_ + h];
        float hz = gh[b * 3 * H_ + H_ + h];
        float hnn = gh[b * 3 * H_ + 2 * H_ + h];
        float r  = 1.f / (1.f + expf(-(ir + hr)));
        float zg = 1.f / (1.f + expf(-(iz + hz)));
        float n  = tanhf(in + r * hnn);
        float hp = hprev[b * H_ + h];
        hn[h] = (1.f - zg) * n + zg * hp;
    }
    __syncthreads();
    float s = 0.f;
    for (int h = threadIdx.x; h < H_; h += blockDim.x) s += hn[h];
    s = blockSum(s);
    if (threadIdx.x == 0) mu_s = s / H_;
    __syncthreads();
    float mu = mu_s;
    float vs = 0.f;
    for (int h = threadIdx.x; h < H_; h += blockDim.x) { float d = hn[h] - mu; vs += d * d; }
    vs = blockSum(vs);
    if (threadIdx.x == 0) sig_s = sqrtf(vs / (float)(H_ - 1));
    __syncthreads();
    float inv = 1.f / (sig_s + LN_EPS_);
    for (int h = threadIdx.x; h < H_; h += blockDim.x) {
        gru_out[b * H_ + h] = (hn[h] - mu) * inv * la[h] + lb[h];
        hnew_out[b * H_ + h] = hn[h];
    }
}

// ---------------- copy-attention scores ----------------
__global__ void k_zc(const float* __restrict__ zclin, const float* __restrict__ gpart,
                     const float* __restrict__ bc, const float* __restrict__ Wv1,
                     const float* __restrict__ bv1, float* __restrict__ zc)
{
    int tb = blockIdx.x;
    int t = tb / B_, b = tb % B_;
    float s = 0.f;
    for (int h = threadIdx.x; h < H_; h += blockDim.x)
        s += Wv1[h] * tanhf(zclin[(size_t)tb * H_ + h] + gpart[b * H_ + h] + bc[h]);
    s = blockSum(s);
    if (threadIdx.x == 0) zc[b * TZ_ + t] = s + bv1[0];
}

// ---------------- joint softmax stats over [gen (V), zc (TZ)] ----------------
__global__ void k_stats(const float* __restrict__ gen, const float* __restrict__ zc,
                        float* __restrict__ mx, float* __restrict__ invs,
                        float* __restrict__ cp)
{
    int b = blockIdx.x;
    __shared__ float mbc, sbc;
    float m = -1e30f;
    for (int v = threadIdx.x; v < V_; v += blockDim.x)
        m = fmaxf(m, gen[(size_t)b * V_ + v]);
    if (threadIdx.x < TZ_) m = fmaxf(m, zc[b * TZ_ + threadIdx.x]);
    m = blockMax(m);
    if (threadIdx.x == 0) mbc = m;
    __syncthreads();
    m = mbc;
    float s = 0.f;
    for (int v = threadIdx.x; v < V_; v += blockDim.x)
        s += expf(gen[(size_t)b * V_ + v] - m);
    if (threadIdx.x < TZ_) s += expf(zc[b * TZ_ + threadIdx.x] - m);
    s = blockSum(s);
    if (threadIdx.x == 0) sbc = s;
    __syncthreads();
    float inv = 1.f / sbc;
    if (threadIdx.x == 0) { mx[b] = m; invs[b] = inv; }
    if (threadIdx.x < TZ_)
        cp[b * TZ_ + threadIdx.x] = expf(zc[b * TZ_ + threadIdx.x] - m) * inv;
}

// ---------------- final: proba = gen_p + mask * (copy_p @ pz_proba) ----------------
__global__ void k_write(const float* __restrict__ gen, const float* __restrict__ pz,
                        const float* __restrict__ mx, const float* __restrict__ invs,
                        const float* __restrict__ cp, float* __restrict__ out)
{
    int idx = blockIdx.x * blockDim.x + threadIdx.x;
    if (idx >= B_ * V_) return;
    int b = idx / V_, v = idx % V_;
    float val = expf(gen[idx] - mx[b]) * invs[b];
    if (v >= FREQ_) {
        float cv = 0.f;
        #pragma unroll
        for (int t = 0; t < TZ_; t++)
            cv += cp[b * TZ_ + t] * pz[((size_t)t * B_ + b) * V_ + v];
        val += cv;
    }
    out[idx] = val;
}

// ---------------- launch ----------------
extern "C" void kernel_launch(void* const* d_in, const int* in_sizes, int n_in,
                              void* d_out, int out_size)
{
    const float* z_enc  = (const float*)d_in[0];
    const float* pz     = (const float*)d_in[1];
    const float* u_enc  = (const float*)d_in[2];
    const int*   mt     = (const int*)  d_in[3];
    const float* hid    = (const float*)d_in[4];
    const float* emb    = (const float*)d_in[5];
    const float* Wa_z   = (const float*)d_in[6];
    const float* ba_z   = (const float*)d_in[7];
    const float* v_z    = (const float*)d_in[8];
    const float* Wa_u   = (const float*)d_in[9];
    const float* ba_u   = (const float*)d_in[10];
    const float* v_u    = (const float*)d_in[11];
    const float* W_ih   = (const float*)d_in[12];
    const float* W_hh   = (const float*)d_in[13];
    const float* b_ih   = (const float*)d_in[14];
    const float* b_hh   = (const float*)d_in[15];
    const float* ln_a   = (const float*)d_in[16];
    const float* ln_b   = (const float*)d_in[17];
    const float* W_proj = (const float*)d_in[18];
    const float* b_proj = (const float*)d_in[19];
    const float* W_c    = (const float*)d_in[20];
    const float* b_c    = (const float*)d_in[21];
    const float* W_v1   = (const float*)d_in[22];
    const float* b_v1   = (const float*)d_in[23];
    float* out = (float*)d_out;

    float* S;
    cudaGetSymbolAddress((void**)&S, g_scratch);
    float* Eu    = S + OFF_EU;
    float* Ez    = S + OFF_EZ;
    float* hpz   = S + OFF_HPZ;
    float* hpu   = S + OFF_HPU;
    float* x     = S + OFF_X;
    float* gi    = S + OFF_GI;
    float* gh    = S + OFF_GH;
    float* gru   = S + OFF_GRU;
    float* gen   = S + OFF_GEN;
    float* gpart = S + OFF_GPART;
    float* zclin = S + OFF_ZCLIN;
    float* scz   = S + OFF_SCZ;
    float* scu   = S + OFF_SCU;
    float* zc    = S + OFF_ZC;
    float* mx    = S + OFF_MX;
    float* invs  = S + OFF_IS;
    float* cp    = S + OFF_CP;

    // 1) embedding gather into x[:, 2H:]
    k_emb<<<B_, 128>>>(emb, mt, x);

    // 2) hidden-part projections: hp = hidden @ Wa[0:H]   (M=32, N=1024, K=1024)
    gemm_tf32<32,128,32,1,4><<<dim3(H_/128, 1), 128>>>(hid, Wa_z, nullptr, hpz, B_, H_, H_, 0);
    gemm_tf32<32,128,32,1,4><<<dim3(H_/128, 1), 128>>>(hid, Wa_u, nullptr, hpu, B_, H_, H_, 0);

    // 3) encoder-part energies: E = enc_flat @ Wa[H:2H]
    gemm_tf32<128,128,32,2,4><<<dim3(H_/128, TZ_*B_/128), 256>>>(
        z_enc, Wa_z + (size_t)H_ * H_, nullptr, Ez, TZ_*B_, H_, H_, 0);
    gemm_tf32<128,128,32,2,4><<<dim3(H_/128, TU_*B_/128), 256>>>(
        u_enc, Wa_u + (size_t)H_ * H_, nullptr, Eu, TU_*B_, H_, H_, 0);

    // 4) attention scores + softmax + context
    k_score<<<TZ_ * B_, 256>>>(Ez, hpz, ba_z, v_z, scz, TZ_);
    k_score<<<TU_ * B_, 256>>>(Eu, hpu, ba_u, v_u, scu, TU_);
    k_softmax_ctx<<<B_, 256>>>(scz, z_enc, x, TZ_, 0);
    k_softmax_ctx<<<B_, 256>>>(scu, u_enc, x, TU_, H_);

    // 5) GRU gates: gi = x @ W_ih^T + b_ih (32x3072x2560) ; gh = h @ W_hh^T + b_hh
    gemm_tf32<32,128,32,1,4><<<dim3(3*H_/128, 1), 128>>>(x,   W_ih, b_ih, gi, B_, 3*H_, XD_, 1);
    gemm_tf32<32,128,32,1,4><<<dim3(3*H_/128, 1), 128>>>(hid, W_hh, b_hh, gh, B_, 3*H_, H_,  1);

    // 6) GRU + layernorm; h_new goes straight to output tail
    k_gru_ln<<<B_, 256>>>(gi, gh, hid, ln_a, ln_b, gru, out + (size_t)B_ * V_);

    // 7) vocab projection + copy-score path
    gemm_tf32<32,128,32,1,4><<<dim3(V_/128, 1), 128>>>(gru, W_proj, b_proj, gen, B_, V_, H_, 0);
    gemm_tf32<32,128,32,1,4><<<dim3(H_/128, 1), 128>>>(gru, W_c + (size_t)H_ * H_, nullptr, gpart, B_, H_, H_, 0);
    gemm_tf32<128,128,32,2,4><<<dim3(H_/128, TZ_*B_/128), 256>>>(
        z_enc, W_c, nullptr, zclin, TZ_*B_, H_, H_, 0);
    k_zc<<<TZ_ * B_, 256>>>(zclin, gpart, b_c, W_v1, b_v1, zc);

    // 8) joint softmax + copy mixture
    k_stats<<<B_, 256>>>(gen, zc, mx, invs, cp);
    k_write<<<(B_ * V_ + 255) / 256, 256>>>(gen, pz, mx, invs, cp, out);
}

// round 4
// speedup vs baseline: 10.4409x; 3.0447x over previous
#include <cuda_runtime.h>
#include <math.h>
#include <stdint.h>

#define B_  32
#define TZ_ 16
#define TU_ 128
#define E_  512
#define H_  1024
#define V_  32000
#define XD_ (E_ + 2*H_)     // 2560
#define LN_EPS_ 1e-3f
#define FREQ_ 4

// ---------------- scratch (device global, no allocs) ----------------
#define OFF_EU     0                         // 4096*1024
#define OFF_EZ     (OFF_EU + TU_*B_*H_)      // 512*1024
#define OFF_HPZ    (OFF_EZ + TZ_*B_*H_)
#define OFF_HPU    (OFF_HPZ + B_*H_)
#define OFF_X      (OFF_HPU + B_*H_)         // B x 2560
#define OFF_GI     (OFF_X + B_*XD_)          // B x 3H
#define OFF_GH     (OFF_GI + B_*3*H_)
#define OFF_GRU    (OFF_GH + B_*3*H_)        // B x H
#define OFF_GEN    (OFF_GRU + B_*H_)         // B x V
#define OFF_GPART  (OFF_GEN + B_*V_)         // B x H
#define OFF_ZCLIN  (OFF_GPART + B_*H_)       // TZ*B x H
#define OFF_SCZ    (OFF_ZCLIN + TZ_*B_*H_)   // B x TZ
#define OFF_SCU    (OFF_SCZ + B_*TZ_)        // B x TU
#define OFF_ZC     (OFF_SCU + B_*TU_)        // B x TZ
#define OFF_MX     (OFF_ZC + B_*TZ_)
#define OFF_IS     (OFF_MX + B_)
#define OFF_CP     (OFF_IS + B_)             // B x TZ
#define OFF_PHP    (OFF_CP + B_*TZ_)         // 4 x 32 x 1024
#define OFF_PGH    (OFF_PHP + 4*B_*H_)       // 2 x 32 x 3072
#define OFF_PGI    (OFF_PGH + 2*B_*3*H_)     // 4 x 32 x 3072
#define OFF_PGP    (OFF_PGI + 4*B_*3*H_)     // 4 x 32 x 1024
#define SCRATCH_TOTAL (OFF_PGP + 4*B_*H_)

__device__ float g_scratch[SCRATCH_TOTAL];

// ---------------- streams & events (created at module load, never in capture) ----
static cudaStream_t g_s1, g_s2, g_s3;
static cudaEvent_t  g_evF, g_e1, g_e2, g_e3, g_eG, g_e4;
namespace {
struct SInit {
    SInit() {
        cudaStreamCreateWithFlags(&g_s1, cudaStreamNonBlocking);
        cudaStreamCreateWithFlags(&g_s2, cudaStreamNonBlocking);
        cudaStreamCreateWithFlags(&g_s3, cudaStreamNonBlocking);
        cudaEventCreateWithFlags(&g_evF, cudaEventDisableTiming);
        cudaEventCreateWithFlags(&g_e1,  cudaEventDisableTiming);
        cudaEventCreateWithFlags(&g_e2,  cudaEventDisableTiming);
        cudaEventCreateWithFlags(&g_e3,  cudaEventDisableTiming);
        cudaEventCreateWithFlags(&g_eG,  cudaEventDisableTiming);
        cudaEventCreateWithFlags(&g_e4,  cudaEventDisableTiming);
    }
};
SInit g_sinit;
}

// ---------------- helpers ----------------
__device__ __forceinline__ uint32_t f2tf32u(float f) {
    uint32_t u;
    asm("cvt.rna.tf32.f32 %0, %1;" : "=r"(u) : "f"(f));
    return u;
}
__device__ __forceinline__ void cp16(void* smem, const void* gmem) {
    uint32_t s = (uint32_t)__cvta_generic_to_shared(smem);
    asm volatile("cp.async.ca.shared.global [%0], [%1], 16;" :: "r"(s), "l"(gmem));
}
__device__ __forceinline__ void cp_commit() { asm volatile("cp.async.commit_group;"); }
template<int N> __device__ __forceinline__ void cp_wait() {
    asm volatile("cp.async.wait_group %0;" :: "n"(N));
}

__device__ __forceinline__ float warpSum(float v) {
    #pragma unroll
    for (int o = 16; o; o >>= 1) v += __shfl_down_sync(0xffffffffu, v, o);
    return v;
}
__device__ __forceinline__ float warpMax(float v) {
    #pragma unroll
    for (int o = 16; o; o >>= 1) v = fmaxf(v, __shfl_down_sync(0xffffffffu, v, o));
    return v;
}
__device__ float blockSum(float v) {
    __shared__ float sh[32];
    int lane = threadIdx.x & 31, wid = threadIdx.x >> 5;
    v = warpSum(v);
    if (lane == 0) sh[wid] = v;
    __syncthreads();
    v = (threadIdx.x < (blockDim.x >> 5)) ? sh[lane] : 0.f;
    if (wid == 0) v = warpSum(v);
    __syncthreads();
    return v;
}
__device__ float blockMax(float v) {
    __shared__ float sh[32];
    int lane = threadIdx.x & 31, wid = threadIdx.x >> 5;
    v = warpMax(v);
    if (lane == 0) sh[wid] = v;
    __syncthreads();
    v = (threadIdx.x < (blockDim.x >> 5)) ? sh[lane] : -1e30f;
    if (wid == 0) v = warpMax(v);
    __syncthreads();
    return v;
}

// ---------------- tf32 tensor-core GEMM, cp.async double-buffered ----------------
// C[M,N] = A[M,K] @ op(B) (+bias per column when bias != null)
// TRANSB=false: B is K x N row-major; TRANSB=true: B is N x K row-major (C = A @ B^T)
// Split-K: grid.z chunks of kLen; each writes C + z*M*N (caller reduces).
// Requires: M%BM==0, N%BN==0, kLen%BK==0.
template<int BM, int BN, int BK, int WARPS_M, int WARPS_N, bool TRANSB>
__global__ __launch_bounds__(32*WARPS_M*WARPS_N)
void gemm_tf32(const float* __restrict__ A, const float* __restrict__ Bm,
               const float* __restrict__ bias, float* __restrict__ C,
               int M, int N, int K, int kLen)
{
    constexpr int NT  = 32 * WARPS_M * WARPS_N;
    constexpr int WM  = BM / WARPS_M;
    constexpr int WN  = BN / WARPS_N;
    constexpr int MT  = WM / 16;
    constexpr int NTL = WN / 8;
    constexpr int BROWS = TRANSB ? BN : BK;
    constexpr int BCOLS = TRANSB ? (BK + 4) : (BN + 8);  // strides: 20 / (BN+8) ≡ 8 mod 32

    __shared__ __align__(16) float As[2][BM][BK + 4];
    __shared__ __align__(16) float Bs[2][BROWS][BCOLS];

    const int tid = threadIdx.x;
    const int wid = tid >> 5, lane = tid & 31;
    const int wm = wid / WARPS_N, wn = wid % WARPS_N;
    const int g = lane >> 2, tg = lane & 3;
    const int bm = blockIdx.y * BM, bn = blockIdx.x * BN;
    const int kStart = blockIdx.z * kLen;
    float* Cout = C + (size_t)blockIdx.z * M * N;

    float acc[MT][NTL][4] = {};

    auto loadStage = [&](int s, int kb) {
        #pragma unroll
        for (int i = tid; i < BM * BK / 4; i += NT) {
            int r = i / (BK / 4), cq = i % (BK / 4);
            cp16(&As[s][r][cq * 4], &A[(size_t)(bm + r) * K + kStart + kb + cq * 4]);
        }
        if (!TRANSB) {
            #pragma unroll
            for (int i = tid; i < BK * BN / 4; i += NT) {
                int r = i / (BN / 4), cq = i % (BN / 4);
                cp16(&Bs[s][r][cq * 4], &Bm[(size_t)(kStart + kb + r) * N + bn + cq * 4]);
            }
        } else {
            #pragma unroll
            for (int i = tid; i < BN * BK / 4; i += NT) {
                int n = i / (BK / 4), cq = i % (BK / 4);
                cp16(&Bs[s][n][cq * 4], &Bm[(size_t)(bn + n) * K + kStart + kb + cq * 4]);
            }
        }
        cp_commit();
    };

    loadStage(0, 0);
    for (int kb = 0; kb < kLen; kb += BK) {
        int cur = (kb / BK) & 1;
        if (kb + BK < kLen) { loadStage(cur ^ 1, kb + BK); cp_wait<1>(); }
        else                { cp_wait<0>(); }
        __syncthreads();

        #pragma unroll
        for (int kk = 0; kk < BK; kk += 8) {
            uint32_t af[MT][4], bf[NTL][2];
            #pragma unroll
            for (int mt = 0; mt < MT; mt++) {
                int r0 = wm * WM + mt * 16 + g;
                af[mt][0] = f2tf32u(As[cur][r0    ][kk + tg    ]);
                af[mt][1] = f2tf32u(As[cur][r0 + 8][kk + tg    ]);
                af[mt][2] = f2tf32u(As[cur][r0    ][kk + tg + 4]);
                af[mt][3] = f2tf32u(As[cur][r0 + 8][kk + tg + 4]);
            }
            #pragma unroll
            for (int nt = 0; nt < NTL; nt++) {
                int c = wn * WN + nt * 8 + g;
                float b0 = TRANSB ? Bs[cur][c][kk + tg    ] : Bs[cur][kk + tg    ][c];
                float b1 = TRANSB ? Bs[cur][c][kk + tg + 4] : Bs[cur][kk + tg + 4][c];
                bf[nt][0] = f2tf32u(b0);
                bf[nt][1] = f2tf32u(b1);
            }
            #pragma unroll
            for (int mt = 0; mt < MT; mt++)
                #pragma unroll
                for (int nt = 0; nt < NTL; nt++) {
                    asm volatile(
                        "mma.sync.aligned.m16n8k8.row.col.f32.tf32.tf32.f32 "
                        "{%0,%1,%2,%3}, {%4,%5,%6,%7}, {%8,%9}, {%0,%1,%2,%3};\n"
                        : "+f"(acc[mt][nt][0]), "+f"(acc[mt][nt][1]),
                          "+f"(acc[mt][nt][2]), "+f"(acc[mt][nt][3])
                        : "r"(af[mt][0]), "r"(af[mt][1]), "r"(af[mt][2]), "r"(af[mt][3]),
                          "r"(bf[nt][0]), "r"(bf[nt][1]));
                }
        }
        __syncthreads();
    }

    #pragma unroll
    for (int mt = 0; mt < MT; mt++) {
        int row0 = bm + wm * WM + mt * 16 + g;
        #pragma unroll
        for (int nt = 0; nt < NTL; nt++) {
            int col = bn + wn * WN + nt * 8 + 2 * tg;
            float bv0 = bias ? bias[col]     : 0.f;
            float bv1 = bias ? bias[col + 1] : 0.f;
            Cout[(size_t)row0 * N + col]           = acc[mt][nt][0] + bv0;
            Cout[(size_t)row0 * N + col + 1]       = acc[mt][nt][1] + bv1;
            Cout[(size_t)(row0 + 8) * N + col]     = acc[mt][nt][2] + bv0;
            Cout[(size_t)(row0 + 8) * N + col + 1] = acc[mt][nt][3] + bv1;
        }
    }
}

// ---------------- split-K reduce (+bias) ----------------
__global__ void k_reduceK(const float* __restrict__ part, const float* __restrict__ bias,
                          float* __restrict__ out, int MN, int N, int S)
{
    int i = blockIdx.x * blockDim.x + threadIdx.x;
    if (i >= MN) return;
    float v = bias ? bias[i % N] : 0.f;
    for (int s = 0; s < S; s++) v += part[(size_t)s * MN + i];
    out[i] = v;
}

// ---------------- embedding gather into x[:, 2H:2H+E] ----------------
__global__ void k_emb(const float* __restrict__ emb, const int* __restrict__ mt,
                      float* __restrict__ x)
{
    int b = blockIdx.x;
    int tok = mt[b];
    for (int e = threadIdx.x; e < E_; e += blockDim.x)
        x[b * XD_ + 2 * H_ + e] = emb[(size_t)tok * E_ + e];
}

// ---------------- attention scores: sc[b,t] = v . tanh(hp[b]+Epart[t,b]+ba) ----------------
__global__ void k_score(const float* __restrict__ Ep, const float* __restrict__ hp,
                        const float* __restrict__ ba, const float* __restrict__ v,
                        float* __restrict__ sc, int T)
{
    int tb = blockIdx.x;          // t*B + b
    int t = tb / B_, b = tb % B_;
    float s = 0.f;
    for (int h = threadIdx.x; h < H_; h += blockDim.x)
        s += v[h] * tanhf(Ep[(size_t)tb * H_ + h] + hp[b * H_ + h] + ba[h]);
    s = blockSum(s);
    if (threadIdx.x == 0) sc[b * T + t] = s;
}

// ---------------- softmax over t + context into x[:, xoff:xoff+H] ----------------
// grid (B, H/256), block 256: each thread one h element
__global__ void k_softmax_ctx(const float* __restrict__ sc, const float* __restrict__ enc,
                              float* __restrict__ x, int T, int xoff)
{
    int b = blockIdx.x;
    int h = blockIdx.y * 256 + threadIdx.x;
    __shared__ float w[TU_];
    if (threadIdx.x == 0) {
        float mx = -1e30f;
        for (int t = 0; t < T; t++) mx = fmaxf(mx, sc[b * T + t]);
        float S = 0.f;
        for (int t = 0; t < T; t++) { float e = expf(sc[b * T + t] - mx); w[t] = e; S += e; }
        float inv = 1.f / S;
        for (int t = 0; t < T; t++) w[t] *= inv;
    }
    __syncthreads();
    float acc = 0.f;
    for (int t = 0; t < T; t++)
        acc += w[t] * enc[((size_t)t * B_ + b) * H_ + h];
    x[b * XD_ + xoff + h] = acc;
}

// ---------------- GRU cell + layernorm (ddof=1, /(sigma+eps)) ----------------
__global__ void k_gru_ln(const float* __restrict__ gi, const float* __restrict__ gh,
                         const float* __restrict__ hprev,
                         const float* __restrict__ la, const float* __restrict__ lb,
                         float* __restrict__ gru_out, float* __restrict__ hnew_out)
{
    int b = blockIdx.x;
    __shared__ float hn[H_];
    __shared__ float mu_s, sig_s;
    for (int h = threadIdx.x; h < H_; h += blockDim.x) {
        float ir = gi[b * 3 * H_ + h];
        float iz = gi[b * 3 * H_ + H_ + h];
        float in = gi[b * 3 * H_ + 2 * H_ + h];
        float hr = gh[b * 3 * H_ + h];
        float hz = gh[b * 3 * H_ + H_ + h];
        float hnn = gh[b * 3 * H_ + 2 * H_ + h];
        float r  = 1.f / (1.f + expf(-(ir + hr)));
        float zg = 1.f / (1.f + expf(-(iz + hz)));
        float n  = tanhf(in + r * hnn);
        float hp = hprev[b * H_ + h];
        hn[h] = (1.f - zg) * n + zg * hp;
    }
    __syncthreads();
    float s = 0.f;
    for (int h = threadIdx.x; h < H_; h += blockDim.x) s += hn[h];
    s = blockSum(s);
    if (threadIdx.x == 0) mu_s = s / H_;
    __syncthreads();
    float mu = mu_s;
    float vs = 0.f;
    for (int h = threadIdx.x; h < H_; h += blockDim.x) { float d = hn[h] - mu; vs += d * d; }
    vs = blockSum(vs);
    if (threadIdx.x == 0) sig_s = sqrtf(vs / (float)(H_ - 1));
    __syncthreads();
    float inv = 1.f / (sig_s + LN_EPS_);
    for (int h = threadIdx.x; h < H_; h += blockDim.x) {
        gru_out[b * H_ + h] = (hn[h] - mu) * inv * la[h] + lb[h];
        hnew_out[b * H_ + h] = hn[h];
    }
}

// ---------------- copy-attention scores ----------------
__global__ void k_zc(const float* __restrict__ zclin, const float* __restrict__ gpart,
                     const float* __restrict__ bc, const float* __restrict__ Wv1,
                     const float* __restrict__ bv1, float* __restrict__ zc)
{
    int tb = blockIdx.x;
    int t = tb / B_, b = tb % B_;
    float s = 0.f;
    for (int h = threadIdx.x; h < H_; h += blockDim.x)
        s += Wv1[h] * tanhf(zclin[(size_t)tb * H_ + h] + gpart[b * H_ + h] + bc[h]);
    s = blockSum(s);
    if (threadIdx.x == 0) zc[b * TZ_ + t] = s + bv1[0];
}

// ---------------- joint softmax stats over [gen (V), zc (TZ)] ----------------
__global__ void k_stats(const float* __restrict__ gen, const float* __restrict__ zc,
                        float* __restrict__ mx, float* __restrict__ invs,
                        float* __restrict__ cp)
{
    int b = blockIdx.x;
    __shared__ float mbc, sbc;
    float m = -1e30f;
    for (int v = threadIdx.x; v < V_; v += blockDim.x)
        m = fmaxf(m, gen[(size_t)b * V_ + v]);
    if (threadIdx.x < TZ_) m = fmaxf(m, zc[b * TZ_ + threadIdx.x]);
    m = blockMax(m);
    if (threadIdx.x == 0) mbc = m;
    __syncthreads();
    m = mbc;
    float s = 0.f;
    for (int v = threadIdx.x; v < V_; v += blockDim.x)
        s += expf(gen[(size_t)b * V_ + v] - m);
    if (threadIdx.x < TZ_) s += expf(zc[b * TZ_ + threadIdx.x] - m);
    s = blockSum(s);
    if (threadIdx.x == 0) sbc = s;
    __syncthreads();
    float inv = 1.f / sbc;
    if (threadIdx.x == 0) { mx[b] = m; invs[b] = inv; }
    if (threadIdx.x < TZ_)
        cp[b * TZ_ + threadIdx.x] = expf(zc[b * TZ_ + threadIdx.x] - m) * inv;
}

// ---------------- final: proba = gen_p + mask * (copy_p @ pz_proba) ----------------
__global__ void k_write(const float* __restrict__ gen, const float* __restrict__ pz,
                        const float* __restrict__ mx, const float* __restrict__ invs,
                        const float* __restrict__ cp, float* __restrict__ out)
{
    int idx = blockIdx.x * blockDim.x + threadIdx.x;
    if (idx >= B_ * V_) return;
    int b = idx / V_, v = idx % V_;
    float val = expf(gen[idx] - mx[b]) * invs[b];
    if (v >= FREQ_) {
        float cv = 0.f;
        #pragma unroll
        for (int t = 0; t < TZ_; t++)
            cv += cp[b * TZ_ + t] * pz[((size_t)t * B_ + b) * V_ + v];
        val += cv;
    }
    out[idx] = val;
}

// ---------------- launch ----------------
extern "C" void kernel_launch(void* const* d_in, const int* in_sizes, int n_in,
                              void* d_out, int out_size)
{
    const float* z_enc  = (const float*)d_in[0];
    const float* pz     = (const float*)d_in[1];
    const float* u_enc  = (const float*)d_in[2];
    const int*   mt     = (const int*)  d_in[3];
    const float* hid    = (const float*)d_in[4];
    const float* emb    = (const float*)d_in[5];
    const float* Wa_z   = (const float*)d_in[6];
    const float* ba_z   = (const float*)d_in[7];
    const float* v_z    = (const float*)d_in[8];
    const float* Wa_u   = (const float*)d_in[9];
    const float* ba_u   = (const float*)d_in[10];
    const float* v_u    = (const float*)d_in[11];
    const float* W_ih   = (const float*)d_in[12];
    const float* W_hh   = (const float*)d_in[13];
    const float* b_ih   = (const float*)d_in[14];
    const float* b_hh   = (const float*)d_in[15];
    const float* ln_a   = (const float*)d_in[16];
    const float* ln_b   = (const float*)d_in[17];
    const float* W_proj = (const float*)d_in[18];
    const float* b_proj = (const float*)d_in[19];
    const float* W_c    = (const float*)d_in[20];
    const float* b_c    = (const float*)d_in[21];
    const float* W_v1   = (const float*)d_in[22];
    const float* b_v1   = (const float*)d_in[23];
    float* out = (float*)d_out;

    float* S;
    cudaGetSymbolAddress((void**)&S, g_scratch);
    float* Eu    = S + OFF_EU;
    float* Ez    = S + OFF_EZ;
    float* hpz   = S + OFF_HPZ;
    float* hpu   = S + OFF_HPU;
    float* x     = S + OFF_X;
    float* gi    = S + OFF_GI;
    float* gh    = S + OFF_GH;
    float* gru   = S + OFF_GRU;
    float* gen   = S + OFF_GEN;
    float* gpart = S + OFF_GPART;
    float* zclin = S + OFF_ZCLIN;
    float* scz   = S + OFF_SCZ;
    float* scu   = S + OFF_SCU;
    float* zc    = S + OFF_ZC;
    float* mx    = S + OFF_MX;
    float* invs  = S + OFF_IS;
    float* cp    = S + OFF_CP;
    float* Php   = S + OFF_PHP;
    float* Pgh   = S + OFF_PGH;
    float* Pgi   = S + OFF_PGI;
    float* Pgp   = S + OFF_PGP;

    // ---------- fork: all four branches depend only on kernel inputs ----------
    cudaEventRecord(g_evF, 0);
    cudaStreamWaitEvent(g_s1, g_evF, 0);
    cudaStreamWaitEvent(g_s2, g_evF, 0);
    cudaStreamWaitEvent(g_s3, g_evF, 0);

    // stream 0 (main): Eu = u_enc @ Wa_u[H:]   (4096 x 1024 x 1024)
    gemm_tf32<128,128,16,2,4,false><<<dim3(H_/128, TU_*B_/128, 1), 256>>>(
        u_enc, Wa_u + (size_t)H_*H_, nullptr, Eu, TU_*B_, H_, H_, H_);

    // s1: Ez = z_enc @ Wa_z[H:]   (512 x 1024 x 1024)
    gemm_tf32<128,128,16,2,4,false><<<dim3(H_/128, TZ_*B_/128, 1), 256, 0, g_s1>>>(
        z_enc, Wa_z + (size_t)H_*H_, nullptr, Ez, TZ_*B_, H_, H_, H_);
    cudaEventRecord(g_e1, g_s1);

    // s2: hpz, hpu (split-K 4), emb, gh (split-K 2)
    gemm_tf32<32,64,16,1,4,false><<<dim3(H_/64, 1, 4), 128, 0, g_s2>>>(
        hid, Wa_z, nullptr, Php, B_, H_, H_, H_/4);
    k_reduceK<<<(B_*H_ + 255)/256, 256, 0, g_s2>>>(Php, nullptr, hpz, B_*H_, H_, 4);
    gemm_tf32<32,64,16,1,4,false><<<dim3(H_/64, 1, 4), 128, 0, g_s2>>>(
        hid, Wa_u, nullptr, Php, B_, H_, H_, H_/4);
    k_reduceK<<<(B_*H_ + 255)/256, 256, 0, g_s2>>>(Php, nullptr, hpu, B_*H_, H_, 4);
    k_emb<<<B_, 128, 0, g_s2>>>(emb, mt, x);
    gemm_tf32<32,64,16,1,4,true><<<dim3(3*H_/64, 1, 2), 128, 0, g_s2>>>(
        hid, W_hh, nullptr, Pgh, B_, 3*H_, H_, H_/2);
    k_reduceK<<<(B_*3*H_ + 255)/256, 256, 0, g_s2>>>(Pgh, b_hh, gh, B_*3*H_, 3*H_, 2);
    cudaEventRecord(g_e2, g_s2);

    // s3: zclin = z_enc @ W_c[0:H]   (512 x 1024 x 1024)
    gemm_tf32<128,128,16,2,4,false><<<dim3(H_/128, TZ_*B_/128, 1), 256, 0, g_s3>>>(
        z_enc, W_c, nullptr, zclin, TZ_*B_, H_, H_, H_);
    cudaEventRecord(g_e3, g_s3);

    // ---------- join Ez + hp branches for the score/context stage ----------
    cudaStreamWaitEvent(0, g_e1, 0);
    cudaStreamWaitEvent(0, g_e2, 0);
    k_score<<<TZ_ * B_, 256>>>(Ez, hpz, ba_z, v_z, scz, TZ_);
    k_score<<<TU_ * B_, 256>>>(Eu, hpu, ba_u, v_u, scu, TU_);
    k_softmax_ctx<<<dim3(B_, H_/256), 256>>>(scz, z_enc, x, TZ_, 0);
    k_softmax_ctx<<<dim3(B_, H_/256), 256>>>(scu, u_enc, x, TU_, H_);

    // gi = x @ W_ih^T + b_ih  (32 x 3072 x 2560, split-K 4)
    gemm_tf32<32,64,16,1,4,true><<<dim3(3*H_/64, 1, 4), 128>>>(
        x, W_ih, nullptr, Pgi, B_, 3*H_, XD_, XD_/4);
    k_reduceK<<<(B_*3*H_ + 255)/256, 256>>>(Pgi, b_ih, gi, B_*3*H_, 3*H_, 4);

    // GRU + layernorm; h_new goes straight to output tail
    k_gru_ln<<<B_, 256>>>(gi, gh, hid, ln_a, ln_b, gru, out + (size_t)B_ * V_);

    // ---------- fork 2: copy path in parallel with the big vocab GEMM ----------
    cudaEventRecord(g_eG, 0);
    cudaStreamWaitEvent(g_s1, g_eG, 0);
    cudaStreamWaitEvent(g_s1, g_e3, 0);   // needs zclin from s3
    gemm_tf32<32,64,16,1,4,false><<<dim3(H_/64, 1, 4), 128, 0, g_s1>>>(
        gru, W_c + (size_t)H_*H_, nullptr, Pgp, B_, H_, H_, H_/4);
    k_reduceK<<<(B_*H_ + 255)/256, 256, 0, g_s1>>>(Pgp, nullptr, gpart, B_*H_, H_, 4);
    k_zc<<<TZ_ * B_, 256, 0, g_s1>>>(zclin, gpart, b_c, W_v1, b_v1, zc);
    cudaEventRecord(g_e4, g_s1);

    // stream 0: gen = gru @ W_proj + b_proj   (32 x 32000 x 1024)
    gemm_tf32<32,64,16,1,4,false><<<dim3(V_/64, 1, 1), 128>>>(
        gru, W_proj, b_proj, gen, B_, V_, H_, H_);

    // ---------- join + final softmax/copy mixture ----------
    cudaStreamWaitEvent(0, g_e4, 0);
    k_stats<<<B_, 256>>>(gen, zc, mx, invs, cp);
    k_write<<<(B_ * V_ + 255) / 256, 256>>>(gen, pz, mx, invs, cp, out);
}